// round 16
// baseline (speedup 1.0000x reference)
#include <cuda_runtime.h>
#include <cuda_fp16.h>
#include <math.h>
#include <float.h>

#define MAXB 16
#define MAXA 33600
#define MAXT 50
#define NCLS 80
#define KC 10
#define LCAP 80
#define LBUF 96
#define BUFCAP 64
#define BUFTOT 80
#define NWI 8
#define NCHB 1056                 // chunk-bbox slots per image (>= (MAXA+128)/32 + 2)
#define INV_LN2 1.4426950408889634f
#define PEN2 (100000.0f * 1.4426950408889634f)

// Scratch (static __device__ globals)
__device__ int    d_cnt [MAXB];
__device__ int    d_mcnt[MAXB];
__device__ int    d_mlist[MAXB][MAXT * KC + 32];
__device__ int    d_tlen[MAXB * MAXT];
__device__ int    d_tlist[MAXB * MAXT][LCAP];
__device__ float4 d_gbox [MAXB][MAXA + 128];     // compacted boxes + zero pad
__device__ float4 d_cbb  [MAXB][NCHB];           // per-32-chunk bounding boxes
__device__ uint2  d_gmeta8[MAXB][MAXA];          // half2(xc,yc) | aidx(16b) | half(rad)
__device__ float  d_gS2  [MAXB][MAXA];
__device__ int    d_gaidx[MAXB][MAXA];
__device__ int    d_pos  [MAXB * MAXA];
__device__ int    d_count[MAXB * MAXA];
__device__ int    d_mint [MAXB * MAXA];
__device__ int    d_dk   [MAXB * MAXT];

__global__ void k0_zero() {
    int i = threadIdx.x;
    if (i < MAXB) { d_cnt[i] = 0; d_mcnt[i] = 0; }
    if (i < MAXB * MAXT) d_tlen[i] = 0;
}

// ---------- warp-parallel selection helpers ----------
__device__ __forceinline__ void sel_cost(float* bufv, int* bufi, int total,
                                         float* topv, int* topi, int lane)
{
    int rounds = min(KC, total);
    for (int r = 0; r < rounds; r++) {
        float v = FLT_MAX; int id = 0x7fffffff; int sl = 0;
        for (int s = lane; s < total; s += 32) {
            float vv = bufv[s]; int ii = bufi[s];
            if (vv < v || (vv == v && ii < id)) { v = vv; id = ii; sl = s; }
        }
        #pragma unroll
        for (int off = 16; off; off >>= 1) {
            float ov = __shfl_xor_sync(0xffffffffu, v, off);
            int   oi = __shfl_xor_sync(0xffffffffu, id, off);
            int   os = __shfl_xor_sync(0xffffffffu, sl, off);
            if (ov < v || (ov == v && oi < id)) { v = ov; id = oi; sl = os; }
        }
        if (lane == 0) { topv[r] = v; topi[r] = id; bufv[sl] = FLT_MAX; bufi[sl] = 0x7fffffff; }
        __syncwarp();
    }
    if (lane >= rounds && lane < KC) { topv[lane] = FLT_MAX; topi[lane] = 0x7fffffff; }
    __syncwarp();
}

__device__ __forceinline__ void sel_iou(float* bufv, int total, float* topv, int lane)
{
    int rounds = min(KC, total);
    for (int r = 0; r < rounds; r++) {
        float v = -1.f; int sl = 0;
        for (int s = lane; s < total; s += 32) {
            float vv = bufv[s];
            if (vv > v) { v = vv; sl = s; }
        }
        #pragma unroll
        for (int off = 16; off; off >>= 1) {
            float ov = __shfl_xor_sync(0xffffffffu, v, off);
            int   os = __shfl_xor_sync(0xffffffffu, sl, off);
            if (ov > v) { v = ov; sl = os; }
        }
        if (lane == 0) { topv[r] = v; bufv[sl] = -1.f; }
        __syncwarp();
    }
    if (lane >= rounds && lane < KC) topv[lane] = -1.f;
    __syncwarp();
}

// K1: fused flags + tlist + softplus + compaction (proven R10/R11 version,
// single-phase 85-col smem).
__global__ __launch_bounds__(128) void k1_anchor(
    const float* __restrict__ pred, const float* __restrict__ target,
    const float* __restrict__ grid, const float* __restrict__ stridem,
    int A, int T)
{
    __shared__ float sp[128 * 85];
    __shared__ float st[MAXT * 8];

    int b    = blockIdx.y;
    int base = blockIdx.x * 128;
    int nrows = min(128, A - base);

    const float* predb = pred + ((size_t)b * A + base) * 84;
    for (int i = threadIdx.x; i < nrows * 84; i += 128) {
        int r = i / 84;
        int c = i - r * 84;
        sp[r * 85 + c] = predb[i];
    }
    for (int i = threadIdx.x; i < T; i += 128) {
        const float* tg = target + ((size_t)b * T + i) * 5;
        float x0 = tg[1], y0 = tg[2], x1 = tg[3], y1 = tg[4];
        st[i * 8 + 0] = x0; st[i * 8 + 1] = y0;
        st[i * 8 + 2] = x1; st[i * 8 + 3] = y1;
        st[i * 8 + 4] = 0.5f * (x0 + x1);
        st[i * 8 + 5] = 0.5f * (y0 + y1);
    }
    __syncthreads();

    int tid  = threadIdx.x;
    int lane = tid & 31;
    bool alive = (tid < nrows);
    int a = base + tid;

    float px0 = 0, py0 = 0, px1 = 0, py1 = 0, xc = 0, yc = 0, rad = 0;
    const float* row = sp + tid * 85;

    if (alive) {
        float strv = stridem[a];
        xc  = (grid[2 * a]     + 0.5f) * strv;
        yc  = (grid[2 * a + 1] + 0.5f) * strv;
        rad = 2.5f * strv;
        px0 = row[0]; py0 = row[1]; px1 = row[2]; py1 = row[3];
    }

    bool anyB = false, anyC = false;
    for (int t = 0; t < T; t++) {
        bool inB = false, inC = false;
        if (alive) {
            float tx0 = st[t * 8 + 0], ty0 = st[t * 8 + 1];
            float tx1 = st[t * 8 + 2], ty1 = st[t * 8 + 3];
            float cxt = st[t * 8 + 4], cyt = st[t * 8 + 5];
            inB = fminf(fminf(xc - tx0, yc - ty0), fminf(tx1 - xc, ty1 - yc)) > 0.f;
            inC = fmaxf(fabsf(xc - cxt), fabsf(yc - cyt)) < rad;
            anyB |= inB; anyC |= inC;
        }
        unsigned mb = __ballot_sync(0xffffffffu, inB && inC);
        if (mb) {
            int bt = b * T + t;
            int leader = __ffs(mb) - 1;
            int wb = 0;
            if (lane == leader) wb = atomicAdd(&d_tlen[bt], __popc(mb));
            wb = __shfl_sync(0xffffffffu, wb, leader);
            if (inB && inC) {
                int slot = wb + __popc(mb & ((1u << lane) - 1u));
                if (slot < LCAP) d_tlist[bt][slot] = a;
            }
        }
    }
    bool iba = alive && (anyB || anyC);

    unsigned m = __ballot_sync(0xffffffffu, iba);
    if (m) {
        float S2 = 0.f;
        if (iba) {
            float P = 1.f;
            int   E = 0;
            #pragma unroll 4
            for (int c = 0; c < NCLS; c++) {
                float e = __expf(row[4 + c]);
                P *= (1.f + e);
                if ((c & 3) == 3) {
                    int bits = __float_as_int(P);
                    E += ((bits >> 23) & 255) - 127;
                    P = __int_as_float((bits & 0x007FFFFF) | 0x3F800000);
                }
            }
            S2 = (float)E + __log2f(P);
        }
        int leader = __ffs(m) - 1;
        int wbase = 0;
        if (lane == leader) wbase = atomicAdd(&d_cnt[b], __popc(m));
        wbase = __shfl_sync(0xffffffffu, wbase, leader);
        if (iba) {
            int pos = wbase + __popc(m & ((1u << lane) - 1u));
            int gi = b * A + a;
            d_pos  [gi] = pos;
            d_count[gi] = 0;
            d_mint [gi] = 0x7fffffff;
            d_gbox [b][pos] = make_float4(px0, py0, px1, py1);
            d_gS2  [b][pos] = S2;
            __half2 hxy = __floats2half2_rn(xc, yc);
            unsigned short hr = __half_as_ushort(__float2half_rn(rad));
            uint2 u;
            u.x = *reinterpret_cast<unsigned*>(&hxy);
            u.y = (unsigned)(a & 0xffff) | ((unsigned)hr << 16);
            d_gmeta8[b][pos] = u;
            d_gaidx [b][pos] = a;
        }
    }
}

// K1cd: zero-pad d_gbox[N..N+127] AND compute per-32-chunk bounding boxes.
// cbb clamps to real boxes (never reads pad) -> no ordering hazard.
__global__ __launch_bounds__(256) void k1cd(int A)
{
    int b = blockIdx.y;
    int w = threadIdx.x >> 5, lane = threadIdx.x & 31;
    int c = blockIdx.x * 8 + w;
    if (c >= NCHB - 2) return;
    int N = d_cnt[b];
    int idx = c * 32 + lane;

    if (idx >= N && idx < MAXA + 128)
        d_gbox[b][idx] = make_float4(0.f, 0.f, 0.f, 0.f);

    if (c * 32 < N) {
        int ii = min(idx, N - 1);
        float4 bx = d_gbox[b][ii];
        float x0 = bx.x, y0 = bx.y, x1 = bx.z, y1 = bx.w;
        #pragma unroll
        for (int off = 16; off; off >>= 1) {
            x0 = fminf(x0, __shfl_xor_sync(0xffffffffu, x0, off));
            y0 = fminf(y0, __shfl_xor_sync(0xffffffffu, y0, off));
            x1 = fmaxf(x1, __shfl_xor_sync(0xffffffffu, x1, off));
            y1 = fmaxf(y1, __shfl_xor_sync(0xffffffffu, y1, off));
        }
        if (lane == 0) d_cbb[b][c] = make_float4(x0, y0, x1, y1);
    } else if (lane == 0) {
        d_cbb[b][c] = make_float4(1e30f, 1e30f, -1e30f, -1e30f);  // never overlaps
    }
}

// K2a: iou top-10 + dyn_k per (b,t). 8 warps/block; warp-uniform chunk-bbox
// screen skips chunks with guaranteed inter==0 for all 32 candidates.
__global__ __launch_bounds__(256) void k2a_iou(
    const float* __restrict__ target, int A, int T)
{
    __shared__ float sbiv[NWI][BUFTOT];
    __shared__ float stiv[NWI][KC];
    __shared__ float tpv[KC];

    int t = blockIdx.x, b = blockIdx.y;
    int w = threadIdx.x >> 5, lane = threadIdx.x & 31;
    int N = d_cnt[b];
    int lo = ((w * N) >> 3) & ~31;
    int hi = (w == NWI - 1) ? N : (((w + 1) * N) >> 3) & ~31;

    const float* tg = target + ((size_t)b * T + t) * 5;
    float tx0 = tg[1], ty0 = tg[2], tx1 = tg[3], ty1 = tg[4];
    float areaT = (tx1 - tx0) * (ty1 - ty0);

    if (lane < KC) stiv[w][lane] = -1.f;
    __syncwarp();

    float thI = 0.f, qs = 0.f;
    int nb = 0;

    const float4* gb = &d_gbox[b][0];
    const float4* cb = &d_cbb[b][0];

    int c0 = lo >> 5, c1 = (hi + 31) >> 5;
    float4 bb = cb[c0];

    for (int c = c0; c < c1; c++) {
        float4 bbn = cb[c + 1];                  // prefetch next chunk bbox

        bool ov = (bb.x < tx1) && (tx0 < bb.z) && (bb.y < ty1) && (ty0 < bb.w);
        if (ov) {                                 // warp-uniform
            float4 bx = gb[(c << 5) + lane];

            float lx = fmaxf(tx0, bx.x), ly = fmaxf(ty0, bx.y);
            float rx = fminf(tx1, bx.z), ry = fminf(ty1, bx.w);
            float ww = fmaxf(rx - lx, 0.f), hh = fmaxf(ry - ly, 0.f);
            float inter = ww * hh;
            float areaP = (bx.z - bx.x) * (bx.w - bx.y);
            float areaS = areaT + areaP;

            bool p = inter > qs * areaS;          // pad boxes: inter=0 -> false
            unsigned mk = __ballot_sync(0xffffffffu, p);
            if (mk) {
                int cnt = __popc(mk);
                if (nb + cnt > BUFCAP) {
                    if (lane < KC) sbiv[w][nb + lane] = stiv[w][lane];
                    __syncwarp();
                    sel_iou(sbiv[w], nb + KC, stiv[w], lane);
                    thI = fmaxf(stiv[w][KC - 1], 0.f);
                    qs = (thI > 0.f) ? __fdividef(thI, 1.f + thI) * (1.f - 1e-5f) : 0.f;
                    nb = 0;
                    p = inter > qs * areaS;
                    mk = __ballot_sync(0xffffffffu, p);
                    cnt = __popc(mk);
                }
                if (p) {
                    float uni = areaS - inter;
                    float iou = inter / fmaxf(uni, 1e-9f);  // exact IEEE (rare path)
                    sbiv[w][nb + __popc(mk & ((1u << lane) - 1u))] = iou;
                }
                nb += cnt;
            }
        }
        bb = bbn;
    }

    if (lane < KC) sbiv[w][nb + lane] = stiv[w][lane];
    __syncwarp();
    sel_iou(sbiv[w], nb + KC, stiv[w], lane);
    __syncthreads();

    if (w == 0) {
        sel_iou(&stiv[0][0], NWI * KC, tpv, lane);
        if (lane == 0) {
            float s = 0.f;
            #pragma unroll
            for (int r = 0; r < KC; r++) { float v = tpv[r]; if (v > 0.f) s += v; }
            int dk = (int)s;
            d_dk[b * T + t] = max(1, min(KC, dk));
        }
    }
}

// K2c: cost top-10 per (b,t) from the per-target list (exact; rare fallback
// full scan). Commit atomics + match list.
__global__ __launch_bounds__(256) void k2c_cost(
    const float* __restrict__ pred, const float* __restrict__ target,
    int A, int T)
{
    __shared__ float bufv[8][LBUF]; __shared__ int bufi[8][LBUF];
    __shared__ float topv[8][KC];   __shared__ int topi[8][KC];

    int w = threadIdx.x >> 5, lane = threadIdx.x & 31;
    int t = blockIdx.x * 8 + w;
    int b = blockIdx.y;
    if (t >= T) return;

    int bt = b * T + t;
    const float* tg = target + ((size_t)b * T + t) * 5;
    int cls = (int)tg[0];
    float tx0 = tg[1], ty0 = tg[2], tx1 = tg[3], ty1 = tg[4];
    float areaT = (tx1 - tx0) * (ty1 - ty0);
    const float* predb = pred + (size_t)b * A * 84;
    int n = d_tlen[bt];

    if (n >= KC) {
        int nn = min(n, LCAP);
        for (int s = lane; s < nn; s += 32) {
            int aidx = d_tlist[bt][s];
            int pos = d_pos[b * A + aidx];
            float4 bx = d_gbox[b][pos];
            float S2 = d_gS2[b][pos];
            float z = predb[(size_t)aidx * 84 + 4 + cls];
            float ct = S2 - z * INV_LN2;
            float lx = fmaxf(tx0, bx.x), ly = fmaxf(ty0, bx.y);
            float rx = fminf(tx1, bx.z), ry = fminf(ty1, bx.w);
            float ww = fmaxf(rx - lx, 0.f), hh = fmaxf(ry - ly, 0.f);
            float inter = ww * hh;
            float areaP = (bx.z - bx.x) * (bx.w - bx.y);
            float uni = areaT + areaP - inter;
            float iou = inter / fmaxf(uni, 1e-9f);
            bufv[w][s] = ct - 3.0f * __log2f(iou + 1e-8f);
            bufi[w][s] = aidx;
        }
        __syncwarp();
        sel_cost(bufv[w], bufi[w], nn, topv[w], topi[w], lane);
    } else {
        int N = d_cnt[b];
        float cxt = 0.5f * (tx0 + tx1), cyt = 0.5f * (ty0 + ty1);
        if (lane < KC) { topv[w][lane] = FLT_MAX; topi[w][lane] = 0x7fffffff; }
        __syncwarp();
        float thv = FLT_MAX; int thi = 0x7fffffff; int nb = 0;

        for (int base = 0; base < N; base += 32) {
            int i = base + lane;
            bool valid = i < N;
            int ii = valid ? i : (N - 1);
            float4 bx = d_gbox[b][ii];
            uint2  mg = d_gmeta8[b][ii];
            float  S2 = d_gS2[b][ii];
            int  aidx = d_gaidx[b][ii];
            float z = predb[(size_t)aidx * 84 + 4 + cls];
            float ct = S2 - z * INV_LN2;
            __half2 hxy = *reinterpret_cast<__half2*>(&mg.x);
            float xc = __low2float(hxy), yc = __high2float(hxy);
            float rad = __half2float(__ushort_as_half((unsigned short)(mg.y >> 16)));

            bool inB = fminf(fminf(xc - tx0, yc - ty0), fminf(tx1 - xc, ty1 - yc)) > 0.f;
            bool inC = fmaxf(fabsf(xc - cxt), fabsf(yc - cyt)) < rad;
            float lx = fmaxf(tx0, bx.x), ly = fmaxf(ty0, bx.y);
            float rx = fminf(tx1, bx.z), ry = fminf(ty1, bx.w);
            float ww = fmaxf(rx - lx, 0.f), hh = fmaxf(ry - ly, 0.f);
            float inter = ww * hh;
            float areaP = (bx.z - bx.x) * (bx.w - bx.y);
            float uni = areaT + areaP - inter;
            float iou = inter / fmaxf(uni, 1e-9f);
            float cost = ct - 3.0f * __log2f(iou + 1e-8f);
            if (!(inB && inC)) cost += PEN2;

            bool pC = valid && (cost < thv || (cost == thv && aidx < thi));
            unsigned mc = __ballot_sync(0xffffffffu, pC);
            if (mc) {
                int cnt = __popc(mc);
                if (nb + cnt > BUFCAP) {
                    if (lane < KC) { bufv[w][nb + lane] = topv[w][lane]; bufi[w][nb + lane] = topi[w][lane]; }
                    __syncwarp();
                    sel_cost(bufv[w], bufi[w], nb + KC, topv[w], topi[w], lane);
                    thv = topv[w][KC - 1]; thi = topi[w][KC - 1];
                    nb = 0;
                    pC = valid && (cost < thv || (cost == thv && aidx < thi));
                    mc = __ballot_sync(0xffffffffu, pC);
                    cnt = __popc(mc);
                }
                if (pC) {
                    int sl = nb + __popc(mc & ((1u << lane) - 1u));
                    bufv[w][sl] = cost; bufi[w][sl] = aidx;
                }
                nb += cnt;
            }
        }
        if (lane < KC) { bufv[w][nb + lane] = topv[w][lane]; bufi[w][nb + lane] = topi[w][lane]; }
        __syncwarp();
        sel_cost(bufv[w], bufi[w], nb + KC, topv[w], topi[w], lane);
    }

    int dk = d_dk[bt];
    if (lane < dk) {
        int id = topi[w][lane];
        if (id != 0x7fffffff) {
            int old = atomicAdd(&d_count[b * A + id], 1);
            atomicMin(&d_mint[b * A + id], t);
            if (old == 0) {
                int p = atomicAdd(&d_mcnt[b], 1);
                d_mlist[b][p] = id;
            }
        }
    }
}

// K4a: streaming default fill (mm=0, box=0, obj=0, cls=80)
__global__ __launch_bounds__(256) void k4a_fill(float* __restrict__ out, int BA)
{
    int n = blockIdx.x * 256 + threadIdx.x;
    int tot = (7 * BA) >> 2;
    if (n < tot) {
        float4 v = (n >= ((6 * BA) >> 2)) ? make_float4(80.f, 80.f, 80.f, 80.f)
                                          : make_float4(0.f, 0.f, 0.f, 0.f);
        ((float4*)out)[n] = v;
    }
}

// K4b: resolve only matched anchors (grid B x 4 for parallelism)
__global__ __launch_bounds__(512) void k4b_resolve(
    const float* __restrict__ pred, const float* __restrict__ target,
    float* __restrict__ out, int A, int T, int B)
{
    __shared__ float st[MAXT * 5];
    int b = blockIdx.x;
    for (int j = threadIdx.x; j < T * 5; j += 512)
        st[j] = target[(size_t)b * T * 5 + j];
    __syncthreads();

    int m = d_mcnt[b];
    int BA = B * A;
    const float* predb = pred + (size_t)b * A * 84;
    for (int j = blockIdx.y * 512 + threadIdx.x; j < m; j += 2048) {
        int id  = d_mlist[b][j];
        int gi  = b * A + id;
        int c   = d_count[gi];
        int pos = d_pos[gi];
        float4 bx = d_gbox[b][pos];
        uint2  mg = d_gmeta8[b][pos];
        float  S2 = d_gS2[b][pos];
        __half2 hxy = *reinterpret_cast<__half2*>(&mg.x);
        float xc = __low2float(hxy), yc = __high2float(hxy);
        float rad = __half2float(__ushort_as_half((unsigned short)(mg.y >> 16)));
        float areaP = (bx.z - bx.x) * (bx.w - bx.y);

        float maxiou = 0.f, bestC = FLT_MAX;
        int bestT = 0;
        bool conflict = (c > 1);

        for (int t = 0; t < T; t++) {
            float tx0 = st[t * 5 + 1], ty0 = st[t * 5 + 2];
            float tx1 = st[t * 5 + 3], ty1 = st[t * 5 + 4];
            float lx = fmaxf(tx0, bx.x), ly = fmaxf(ty0, bx.y);
            float rx = fminf(tx1, bx.z), ry = fminf(ty1, bx.w);
            float w2 = fmaxf(rx - lx, 0.f), h2 = fmaxf(ry - ly, 0.f);
            float inter = w2 * h2;
            float areaT = (tx1 - tx0) * (ty1 - ty0);
            float uni = areaT + areaP - inter;
            float iou = inter / fmaxf(uni, 1e-9f);
            maxiou = fmaxf(maxiou, iou);
            if (conflict) {
                int cls = (int)st[t * 5 + 0];
                float z = predb[(size_t)id * 84 + 4 + cls];
                float ct = S2 - z * INV_LN2;
                float cx = 0.5f * (tx0 + tx1), cy = 0.5f * (ty0 + ty1);
                bool inB = fminf(fminf(xc - tx0, yc - ty0), fminf(tx1 - xc, ty1 - yc)) > 0.f;
                bool inC = fmaxf(fabsf(xc - cx), fabsf(yc - cy)) < rad;
                float cost = ct - 3.0f * __log2f(iou + 1e-8f);
                if (!(inB && inC)) cost += PEN2;
                if (cost < bestC) { bestC = cost; bestT = t; }
            }
        }

        int tt = conflict ? bestT : d_mint[gi];
        out[gi] = 1.f;
        ((float4*)(out + BA))[gi] = make_float4(st[tt * 5 + 1], st[tt * 5 + 2],
                                                st[tt * 5 + 3], st[tt * 5 + 4]);
        out[(size_t)5 * BA + gi] = maxiou;
        out[(size_t)6 * BA + gi] = st[tt * 5 + 0];
    }
}

extern "C" void kernel_launch(void* const* d_in, const int* in_sizes, int n_in,
                              void* d_out, int out_size)
{
    const float* pred    = (const float*)d_in[0];
    const float* target  = (const float*)d_in[1];
    const float* grid    = (const float*)d_in[2];
    const float* stridem = (const float*)d_in[3];

    int A = in_sizes[3];
    int B = in_sizes[0] / (A * 84);
    int T = in_sizes[1] / (B * 5);
    int BA = B * A;

    k0_zero<<<1, 1024>>>();

    dim3 g1((A + 127) / 128, B);
    k1_anchor<<<g1, 128>>>(pred, target, grid, stridem, A, T);

    dim3 gcd((NCHB - 2 + 7) / 8, B);
    k1cd<<<gcd, 256>>>(A);

    dim3 g2a(T, B);
    k2a_iou<<<g2a, 256>>>(target, A, T);       // profiler slot 4

    dim3 g2c((T + 7) / 8, B);
    k2c_cost<<<g2c, 256>>>(pred, target, A, T);

    int tot4 = (7 * BA) / 4;
    k4a_fill<<<(tot4 + 255) / 256, 256>>>((float*)d_out, BA);

    dim3 g4b(B, 4);
    k4b_resolve<<<g4b, 512>>>(pred, target, (float*)d_out, A, T, B);
}

// round 17
// speedup vs baseline: 1.1414x; 1.1414x over previous
#include <cuda_runtime.h>
#include <cuda_fp16.h>
#include <math.h>
#include <float.h>

#define MAXB 16
#define MAXA 33600
#define MAXT 50
#define NCLS 80
#define KC 10
#define LCAP 80
#define LBUF 96
#define BUFCAP 64
#define BUFTOT 80
#define NWI 8
#define INV_LN2 1.4426950408889634f
#define PEN2 (100000.0f * 1.4426950408889634f)

// Scratch (static __device__ globals)
__device__ int    d_cnt [MAXB];
__device__ int    d_mcnt[MAXB];
__device__ int    d_mlist[MAXB][MAXT * KC + 32];
__device__ int    d_tlen[MAXB * MAXT];
__device__ int    d_tlist[MAXB * MAXT][LCAP];
__device__ float4 d_gbox [MAXB][MAXA + 128];     // compacted boxes + zero pad
__device__ uint2  d_gmeta8[MAXB][MAXA];          // half2(xc,yc) | aidx(16b) | half(rad)
__device__ float  d_gS2  [MAXB][MAXA];
__device__ int    d_gaidx[MAXB][MAXA];
__device__ int    d_pos  [MAXB * MAXA];
__device__ int    d_count[MAXB * MAXA];
__device__ int    d_mint [MAXB * MAXA];
__device__ int    d_dk   [MAXB * MAXT];

__global__ void k0a_zero() {
    if (threadIdx.x < MAXB) { d_cnt[threadIdx.x] = 0; d_mcnt[threadIdx.x] = 0; }
}
__global__ void k0b_zero() {
    int i = threadIdx.x;
    if (i < MAXB * MAXT) d_tlen[i] = 0;
}

// ---------- warp-parallel selection helpers ----------
__device__ __forceinline__ void sel_cost(float* bufv, int* bufi, int total,
                                         float* topv, int* topi, int lane)
{
    int rounds = min(KC, total);
    for (int r = 0; r < rounds; r++) {
        float v = FLT_MAX; int id = 0x7fffffff; int sl = 0;
        for (int s = lane; s < total; s += 32) {
            float vv = bufv[s]; int ii = bufi[s];
            if (vv < v || (vv == v && ii < id)) { v = vv; id = ii; sl = s; }
        }
        #pragma unroll
        for (int off = 16; off; off >>= 1) {
            float ov = __shfl_xor_sync(0xffffffffu, v, off);
            int   oi = __shfl_xor_sync(0xffffffffu, id, off);
            int   os = __shfl_xor_sync(0xffffffffu, sl, off);
            if (ov < v || (ov == v && oi < id)) { v = ov; id = oi; sl = os; }
        }
        if (lane == 0) { topv[r] = v; topi[r] = id; bufv[sl] = FLT_MAX; bufi[sl] = 0x7fffffff; }
        __syncwarp();
    }
    if (lane >= rounds && lane < KC) { topv[lane] = FLT_MAX; topi[lane] = 0x7fffffff; }
    __syncwarp();
}

__device__ __forceinline__ void sel_iou(float* bufv, int total, float* topv, int lane)
{
    int rounds = min(KC, total);
    for (int r = 0; r < rounds; r++) {
        float v = -1.f; int sl = 0;
        for (int s = lane; s < total; s += 32) {
            float vv = bufv[s];
            if (vv > v) { v = vv; sl = s; }
        }
        #pragma unroll
        for (int off = 16; off; off >>= 1) {
            float ov = __shfl_xor_sync(0xffffffffu, v, off);
            int   os = __shfl_xor_sync(0xffffffffu, sl, off);
            if (ov > v) { v = ov; sl = os; }
        }
        if (lane == 0) { topv[r] = v; bufv[sl] = -1.f; }
        __syncwarp();
    }
    if (lane >= rounds && lane < KC) topv[lane] = -1.f;
    __syncwarp();
}

// K1: fused flags + tlist + softplus + compaction. Float4 staging end-to-end:
// rows are 21 float4s; 8-thread LDS.128 phases at 336B stride are
// conflict-free (offsets {0,80,32,112,64,16,96,48} mod 128).
__global__ __launch_bounds__(128) void k1_anchor(
    const float* __restrict__ pred, const float* __restrict__ target,
    const float* __restrict__ grid, const float* __restrict__ stridem,
    int A, int T)
{
    __shared__ float4 sp4[128 * 21];
    __shared__ float st[MAXT * 8];

    int b    = blockIdx.y;
    int base = blockIdx.x * 128;
    int nrows = min(128, A - base);
    int tid  = threadIdx.x;
    int lane = tid & 31;

    const float4* p4 = reinterpret_cast<const float4*>(pred + ((size_t)b * A + base) * 84);
    for (int i = tid; i < nrows * 21; i += 128)
        sp4[i] = p4[i];

    for (int i = tid; i < T; i += 128) {
        const float* tg = target + ((size_t)b * T + i) * 5;
        float x0 = tg[1], y0 = tg[2], x1 = tg[3], y1 = tg[4];
        st[i * 8 + 0] = x0; st[i * 8 + 1] = y0;
        st[i * 8 + 2] = x1; st[i * 8 + 3] = y1;
        st[i * 8 + 4] = 0.5f * (x0 + x1);
        st[i * 8 + 5] = 0.5f * (y0 + y1);
    }
    __syncthreads();

    bool alive = (tid < nrows);
    int a = base + tid;
    const float4* row4 = sp4 + tid * 21;

    float xc = 0, yc = 0, rad = 0;
    float4 box = make_float4(0.f, 0.f, 0.f, 0.f);
    if (alive) {
        float strv = stridem[a];
        xc  = (grid[2 * a]     + 0.5f) * strv;
        yc  = (grid[2 * a + 1] + 0.5f) * strv;
        rad = 2.5f * strv;
        box = row4[0];
    }

    bool anyB = false, anyC = false;
    for (int t = 0; t < T; t++) {
        bool inB = false, inC = false;
        if (alive) {
            float tx0 = st[t * 8 + 0], ty0 = st[t * 8 + 1];
            float tx1 = st[t * 8 + 2], ty1 = st[t * 8 + 3];
            float cxt = st[t * 8 + 4], cyt = st[t * 8 + 5];
            inB = fminf(fminf(xc - tx0, yc - ty0), fminf(tx1 - xc, ty1 - yc)) > 0.f;
            inC = fmaxf(fabsf(xc - cxt), fabsf(yc - cyt)) < rad;
            anyB |= inB; anyC |= inC;
        }
        unsigned mb = __ballot_sync(0xffffffffu, inB && inC);
        if (mb) {
            int bt = b * T + t;
            int leader = __ffs(mb) - 1;
            int wb = 0;
            if (lane == leader) wb = atomicAdd(&d_tlen[bt], __popc(mb));
            wb = __shfl_sync(0xffffffffu, wb, leader);
            if (inB && inC) {
                int slot = wb + __popc(mb & ((1u << lane) - 1u));
                if (slot < LCAP) d_tlist[bt][slot] = a;
            }
        }
    }
    bool iba = alive && (anyB || anyC);

    unsigned m = __ballot_sync(0xffffffffu, iba);
    if (m) {
        float S2 = 0.f;
        if (iba) {
            float P = 1.f;
            int   E = 0;
            #pragma unroll 5
            for (int q = 0; q < 20; q++) {        // logits in float4 groups of 4
                float4 z4 = row4[1 + q];
                P *= (1.f + __expf(z4.x));
                P *= (1.f + __expf(z4.y));
                P *= (1.f + __expf(z4.z));
                P *= (1.f + __expf(z4.w));
                int bits = __float_as_int(P);     // renorm after each group of 4
                E += ((bits >> 23) & 255) - 127;
                P = __int_as_float((bits & 0x007FFFFF) | 0x3F800000);
            }
            S2 = (float)E + __log2f(P);
        }
        int leader = __ffs(m) - 1;
        int wbase = 0;
        if (lane == leader) wbase = atomicAdd(&d_cnt[b], __popc(m));
        wbase = __shfl_sync(0xffffffffu, wbase, leader);
        if (iba) {
            int pos = wbase + __popc(m & ((1u << lane) - 1u));
            int gi = b * A + a;
            d_pos  [gi] = pos;
            d_count[gi] = 0;
            d_mint [gi] = 0x7fffffff;
            d_gbox [b][pos] = box;
            d_gS2  [b][pos] = S2;
            __half2 hxy = __floats2half2_rn(xc, yc);
            unsigned short hr = __half_as_ushort(__float2half_rn(rad));
            uint2 u;
            u.x = *reinterpret_cast<unsigned*>(&hxy);
            u.y = (unsigned)(a & 0xffff) | ((unsigned)hr << 16);
            d_gmeta8[b][pos] = u;
            d_gaidx [b][pos] = a;
        }
    }
}

// K1c: pad d_gbox[N..N+127] with zero boxes so k2a needs no bounds checks.
__global__ void k1c_pad() {
    int b = blockIdx.x;
    int pos = d_cnt[b] + threadIdx.x;     // 128 threads
    if (pos < MAXA + 128) d_gbox[b][pos] = make_float4(0.f, 0.f, 0.f, 0.f);
}

// K2a: iou top-10 + dyn_k per (b,t). 8 warps/block on 32-aligned slices of
// the padded candidate array: NO bounds logic in the hot loop (R15-proven).
__global__ __launch_bounds__(256) void k2a_iou(
    const float* __restrict__ target, int A, int T)
{
    __shared__ float sbiv[NWI][BUFTOT];
    __shared__ float stiv[NWI][KC];
    __shared__ float tpv[KC];

    int t = blockIdx.x, b = blockIdx.y;
    int w = threadIdx.x >> 5, lane = threadIdx.x & 31;
    int N = d_cnt[b];
    int lo = ((w * N) >> 3) & ~31;
    int hi = (w == NWI - 1) ? N : (((w + 1) * N) >> 3) & ~31;

    const float* tg = target + ((size_t)b * T + t) * 5;
    float tx0 = tg[1], ty0 = tg[2], tx1 = tg[3], ty1 = tg[4];
    float areaT = (tx1 - tx0) * (ty1 - ty0);

    if (lane < KC) stiv[w][lane] = -1.f;
    __syncwarp();

    float thI = 0.f, qs = 0.f;
    int nb = 0;

    const float4* gb = &d_gbox[b][0];
    float4 bx = gb[lo + lane];

    for (int i = lo; i < hi; i += 32) {
        float4 nxt = gb[i + 32 + lane];          // unconditional (padded)

        float lx = fmaxf(tx0, bx.x), ly = fmaxf(ty0, bx.y);
        float rx = fminf(tx1, bx.z), ry = fminf(ty1, bx.w);
        float ww = fmaxf(rx - lx, 0.f), hh = fmaxf(ry - ly, 0.f);
        float inter = ww * hh;
        float areaP = (bx.z - bx.x) * (bx.w - bx.y);
        float areaS = areaT + areaP;

        bool p = inter > qs * areaS;             // pad boxes: inter=0 -> false
        unsigned mk = __ballot_sync(0xffffffffu, p);
        if (mk) {
            int cnt = __popc(mk);
            if (nb + cnt > BUFCAP) {
                if (lane < KC) sbiv[w][nb + lane] = stiv[w][lane];
                __syncwarp();
                sel_iou(sbiv[w], nb + KC, stiv[w], lane);
                thI = fmaxf(stiv[w][KC - 1], 0.f);
                qs = (thI > 0.f) ? __fdividef(thI, 1.f + thI) * (1.f - 1e-5f) : 0.f;
                nb = 0;
                p = inter > qs * areaS;
                mk = __ballot_sync(0xffffffffu, p);
                cnt = __popc(mk);
            }
            if (p) {
                float uni = areaS - inter;
                float iou = inter / fmaxf(uni, 1e-9f);   // exact IEEE (rare path)
                sbiv[w][nb + __popc(mk & ((1u << lane) - 1u))] = iou;
            }
            nb += cnt;
        }
        bx = nxt;
    }

    if (lane < KC) sbiv[w][nb + lane] = stiv[w][lane];
    __syncwarp();
    sel_iou(sbiv[w], nb + KC, stiv[w], lane);
    __syncthreads();

    if (w == 0) {
        sel_iou(&stiv[0][0], NWI * KC, tpv, lane);
        if (lane == 0) {
            float s = 0.f;
            #pragma unroll
            for (int r = 0; r < KC; r++) { float v = tpv[r]; if (v > 0.f) s += v; }
            int dk = (int)s;
            d_dk[b * T + t] = max(1, min(KC, dk));
        }
    }
}

// K2c: cost top-10 per (b,t) from the per-target list (exact; rare fallback
// full scan). Commit atomics + match list.
__global__ __launch_bounds__(256) void k2c_cost(
    const float* __restrict__ pred, const float* __restrict__ target,
    int A, int T)
{
    __shared__ float bufv[8][LBUF]; __shared__ int bufi[8][LBUF];
    __shared__ float topv[8][KC];   __shared__ int topi[8][KC];

    int w = threadIdx.x >> 5, lane = threadIdx.x & 31;
    int t = blockIdx.x * 8 + w;
    int b = blockIdx.y;
    if (t >= T) return;

    int bt = b * T + t;
    const float* tg = target + ((size_t)b * T + t) * 5;
    int cls = (int)tg[0];
    float tx0 = tg[1], ty0 = tg[2], tx1 = tg[3], ty1 = tg[4];
    float areaT = (tx1 - tx0) * (ty1 - ty0);
    const float* predb = pred + (size_t)b * A * 84;
    int n = d_tlen[bt];

    if (n >= KC) {
        int nn = min(n, LCAP);
        for (int s = lane; s < nn; s += 32) {
            int aidx = d_tlist[bt][s];
            int pos = d_pos[b * A + aidx];
            float4 bx = d_gbox[b][pos];
            float S2 = d_gS2[b][pos];
            float z = predb[(size_t)aidx * 84 + 4 + cls];
            float ct = S2 - z * INV_LN2;
            float lx = fmaxf(tx0, bx.x), ly = fmaxf(ty0, bx.y);
            float rx = fminf(tx1, bx.z), ry = fminf(ty1, bx.w);
            float ww = fmaxf(rx - lx, 0.f), hh = fmaxf(ry - ly, 0.f);
            float inter = ww * hh;
            float areaP = (bx.z - bx.x) * (bx.w - bx.y);
            float uni = areaT + areaP - inter;
            float iou = inter / fmaxf(uni, 1e-9f);
            bufv[w][s] = ct - 3.0f * __log2f(iou + 1e-8f);
            bufi[w][s] = aidx;
        }
        __syncwarp();
        sel_cost(bufv[w], bufi[w], nn, topv[w], topi[w], lane);
    } else {
        int N = d_cnt[b];
        float cxt = 0.5f * (tx0 + tx1), cyt = 0.5f * (ty0 + ty1);
        if (lane < KC) { topv[w][lane] = FLT_MAX; topi[w][lane] = 0x7fffffff; }
        __syncwarp();
        float thv = FLT_MAX; int thi = 0x7fffffff; int nb = 0;

        for (int base = 0; base < N; base += 32) {
            int i = base + lane;
            bool valid = i < N;
            int ii = valid ? i : (N - 1);
            float4 bx = d_gbox[b][ii];
            uint2  mg = d_gmeta8[b][ii];
            float  S2 = d_gS2[b][ii];
            int  aidx = d_gaidx[b][ii];
            float z = predb[(size_t)aidx * 84 + 4 + cls];
            float ct = S2 - z * INV_LN2;
            __half2 hxy = *reinterpret_cast<__half2*>(&mg.x);
            float xc = __low2float(hxy), yc = __high2float(hxy);
            float rad = __half2float(__ushort_as_half((unsigned short)(mg.y >> 16)));

            bool inB = fminf(fminf(xc - tx0, yc - ty0), fminf(tx1 - xc, ty1 - yc)) > 0.f;
            bool inC = fmaxf(fabsf(xc - cxt), fabsf(yc - cyt)) < rad;
            float lx = fmaxf(tx0, bx.x), ly = fmaxf(ty0, bx.y);
            float rx = fminf(tx1, bx.z), ry = fminf(ty1, bx.w);
            float ww = fmaxf(rx - lx, 0.f), hh = fmaxf(ry - ly, 0.f);
            float inter = ww * hh;
            float areaP = (bx.z - bx.x) * (bx.w - bx.y);
            float uni = areaT + areaP - inter;
            float iou = inter / fmaxf(uni, 1e-9f);
            float cost = ct - 3.0f * __log2f(iou + 1e-8f);
            if (!(inB && inC)) cost += PEN2;

            bool pC = valid && (cost < thv || (cost == thv && aidx < thi));
            unsigned mc = __ballot_sync(0xffffffffu, pC);
            if (mc) {
                int cnt = __popc(mc);
                if (nb + cnt > BUFCAP) {
                    if (lane < KC) { bufv[w][nb + lane] = topv[w][lane]; bufi[w][nb + lane] = topi[w][lane]; }
                    __syncwarp();
                    sel_cost(bufv[w], bufi[w], nb + KC, topv[w], topi[w], lane);
                    thv = topv[w][KC - 1]; thi = topi[w][KC - 1];
                    nb = 0;
                    pC = valid && (cost < thv || (cost == thv && aidx < thi));
                    mc = __ballot_sync(0xffffffffu, pC);
                    cnt = __popc(mc);
                }
                if (pC) {
                    int sl = nb + __popc(mc & ((1u << lane) - 1u));
                    bufv[w][sl] = cost; bufi[w][sl] = aidx;
                }
                nb += cnt;
            }
        }
        if (lane < KC) { bufv[w][nb + lane] = topv[w][lane]; bufi[w][nb + lane] = topi[w][lane]; }
        __syncwarp();
        sel_cost(bufv[w], bufi[w], nb + KC, topv[w], topi[w], lane);
    }

    int dk = d_dk[bt];
    if (lane < dk) {
        int id = topi[w][lane];
        if (id != 0x7fffffff) {
            int old = atomicAdd(&d_count[b * A + id], 1);
            atomicMin(&d_mint[b * A + id], t);
            if (old == 0) {
                int p = atomicAdd(&d_mcnt[b], 1);
                d_mlist[b][p] = id;
            }
        }
    }
}

// K4a: streaming default fill (mm=0, box=0, obj=0, cls=80)
__global__ __launch_bounds__(256) void k4a_fill(float* __restrict__ out, int BA)
{
    int n = blockIdx.x * 256 + threadIdx.x;
    int tot = (7 * BA) >> 2;
    if (n < tot) {
        float4 v = (n >= ((6 * BA) >> 2)) ? make_float4(80.f, 80.f, 80.f, 80.f)
                                          : make_float4(0.f, 0.f, 0.f, 0.f);
        ((float4*)out)[n] = v;
    }
}

// K4b: resolve only matched anchors (grid B x 4 for parallelism)
__global__ __launch_bounds__(512) void k4b_resolve(
    const float* __restrict__ pred, const float* __restrict__ target,
    float* __restrict__ out, int A, int T, int B)
{
    __shared__ float st[MAXT * 5];
    int b = blockIdx.x;
    for (int j = threadIdx.x; j < T * 5; j += 512)
        st[j] = target[(size_t)b * T * 5 + j];
    __syncthreads();

    int m = d_mcnt[b];
    int BA = B * A;
    const float* predb = pred + (size_t)b * A * 84;
    for (int j = blockIdx.y * 512 + threadIdx.x; j < m; j += 2048) {
        int id  = d_mlist[b][j];
        int gi  = b * A + id;
        int c   = d_count[gi];
        int pos = d_pos[gi];
        float4 bx = d_gbox[b][pos];
        uint2  mg = d_gmeta8[b][pos];
        float  S2 = d_gS2[b][pos];
        __half2 hxy = *reinterpret_cast<__half2*>(&mg.x);
        float xc = __low2float(hxy), yc = __high2float(hxy);
        float rad = __half2float(__ushort_as_half((unsigned short)(mg.y >> 16)));
        float areaP = (bx.z - bx.x) * (bx.w - bx.y);

        float maxiou = 0.f, bestC = FLT_MAX;
        int bestT = 0;
        bool conflict = (c > 1);

        for (int t = 0; t < T; t++) {
            float tx0 = st[t * 5 + 1], ty0 = st[t * 5 + 2];
            float tx1 = st[t * 5 + 3], ty1 = st[t * 5 + 4];
            float lx = fmaxf(tx0, bx.x), ly = fmaxf(ty0, bx.y);
            float rx = fminf(tx1, bx.z), ry = fminf(ty1, bx.w);
            float w2 = fmaxf(rx - lx, 0.f), h2 = fmaxf(ry - ly, 0.f);
            float inter = w2 * h2;
            float areaT = (tx1 - tx0) * (ty1 - ty0);
            float uni = areaT + areaP - inter;
            float iou = inter / fmaxf(uni, 1e-9f);
            maxiou = fmaxf(maxiou, iou);
            if (conflict) {
                int cls = (int)st[t * 5 + 0];
                float z = predb[(size_t)id * 84 + 4 + cls];
                float ct = S2 - z * INV_LN2;
                float cx = 0.5f * (tx0 + tx1), cy = 0.5f * (ty0 + ty1);
                bool inB = fminf(fminf(xc - tx0, yc - ty0), fminf(tx1 - xc, ty1 - yc)) > 0.f;
                bool inC = fmaxf(fabsf(xc - cx), fabsf(yc - cy)) < rad;
                float cost = ct - 3.0f * __log2f(iou + 1e-8f);
                if (!(inB && inC)) cost += PEN2;
                if (cost < bestC) { bestC = cost; bestT = t; }
            }
        }

        int tt = conflict ? bestT : d_mint[gi];
        out[gi] = 1.f;
        ((float4*)(out + BA))[gi] = make_float4(st[tt * 5 + 1], st[tt * 5 + 2],
                                                st[tt * 5 + 3], st[tt * 5 + 4]);
        out[(size_t)5 * BA + gi] = maxiou;
        out[(size_t)6 * BA + gi] = st[tt * 5 + 0];
    }
}

extern "C" void kernel_launch(void* const* d_in, const int* in_sizes, int n_in,
                              void* d_out, int out_size)
{
    const float* pred    = (const float*)d_in[0];
    const float* target  = (const float*)d_in[1];
    const float* grid    = (const float*)d_in[2];
    const float* stridem = (const float*)d_in[3];

    int A = in_sizes[3];
    int B = in_sizes[0] / (A * 84);
    int T = in_sizes[1] / (B * 5);
    int BA = B * A;

    k0a_zero<<<1, 32>>>();
    k0b_zero<<<1, 1024>>>();

    int tot4 = (7 * BA) / 4;
    k4a_fill<<<(tot4 + 255) / 256, 256>>>((float*)d_out, BA);

    dim3 g1((A + 127) / 128, B);
    k1_anchor<<<g1, 128>>>(pred, target, grid, stridem, A, T);   // profiler slot 4

    k1c_pad<<<B, 128>>>();

    dim3 g2a(T, B);
    k2a_iou<<<g2a, 256>>>(target, A, T);

    dim3 g2c((T + 7) / 8, B);
    k2c_cost<<<g2c, 256>>>(pred, target, A, T);

    dim3 g4b(B, 4);
    k4b_resolve<<<g4b, 512>>>(pred, target, (float*)d_out, A, T, B);
}